// round 2
// baseline (speedup 1.0000x reference)
#include <cuda_runtime.h>
#include <cuda_fp16.h>

// Problem constants
#define Bsz 64
#define Ssz 2048
#define Fsz 1024
#define Hsz 1024
#define Lsz 128
#define NCsz 16
#define MROWS (Bsz * Ssz)   // 131072
#define NSEQ  (Bsz * NCsz)  // 1024

// ---------------- scratch (static device allocations) ----------------
__device__ __half g_xh[(size_t)MROWS * Fsz];      // 256 MB  fp16 inputs
__device__ float  g_xproj[(size_t)MROWS * Hsz];   // 512 MB  x @ W_ih^T + bias
__device__ __half g_wih[Hsz * Fsz];               // 2 MB
__device__ __half g_whh[Hsz * Hsz];               // 2 MB
__device__ __half g_hbuf[2][NSEQ * Hsz];          // 4 MB ping-pong hidden state
__device__ float  g_bias[Hsz];

// ---------------- small helpers ----------------
__device__ __forceinline__ unsigned smem_u32(const void* p) {
    return (unsigned)__cvta_generic_to_shared(p);
}
__device__ __forceinline__ void ldmatrix_x4(unsigned& r0, unsigned& r1, unsigned& r2, unsigned& r3, unsigned addr) {
    asm volatile("ldmatrix.sync.aligned.m8n8.x4.shared.b16 {%0,%1,%2,%3}, [%4];\n"
                 : "=r"(r0), "=r"(r1), "=r"(r2), "=r"(r3) : "r"(addr));
}
__device__ __forceinline__ void mma16816(float* c, const unsigned* a, const unsigned* b) {
    asm volatile("mma.sync.aligned.m16n8k16.row.col.f32.f16.f16.f32 "
                 "{%0,%1,%2,%3}, {%4,%5,%6,%7}, {%8,%9}, {%0,%1,%2,%3};\n"
                 : "+f"(c[0]), "+f"(c[1]), "+f"(c[2]), "+f"(c[3])
                 : "r"(a[0]), "r"(a[1]), "r"(a[2]), "r"(a[3]), "r"(b[0]), "r"(b[1]));
}
__device__ __forceinline__ void cp_async16(unsigned saddr, const void* gaddr) {
    asm volatile("cp.async.cg.shared.global [%0], [%1], 16;\n" :: "r"(saddr), "l"(gaddr));
}
__device__ __forceinline__ void cp_commit() { asm volatile("cp.async.commit_group;\n"); }
__device__ __forceinline__ void cp_wait0()  { asm volatile("cp.async.wait_group 0;\n"); }

// ---------------- conversion / prep kernels ----------------
__global__ void convert_x_kernel(const float* __restrict__ x) {
    size_t i = ((size_t)blockIdx.x * blockDim.x + threadIdx.x) * 4;
    float4 v = *(const float4*)(x + i);
    *(__half2*)(g_xh + i)     = __floats2half2_rn(v.x, v.y);
    *(__half2*)(g_xh + i + 2) = __floats2half2_rn(v.z, v.w);
}

__global__ void prep_kernel(const float* __restrict__ wih, const float* __restrict__ whh,
                            const float* __restrict__ bih, const float* __restrict__ bhh) {
    int i = blockIdx.x * blockDim.x + threadIdx.x;   // 0 .. 1048575
    g_wih[i] = __float2half_rn(wih[i]);
    g_whh[i] = __float2half_rn(whh[i]);
    g_hbuf[0][i] = __float2half_rn(0.0f);
    if (i < Hsz) g_bias[i] = bih[i] + bhh[i];
}

// ---------------- 128x64 GEMM mainloop (TN, fp16 x fp16 -> fp32) ----------------
// A: [*, 1024] row-major fp16 (k contiguous), rows m0..m0+127
// B: [1024, 1024] row-major fp16 (k contiguous), rows n0..n0+63  (i.e. W, computing A @ W^T)
// 128 threads = 4 warps, warp grid 2x2, warp tile 64x32, BK=32, double-buffered cp.async.
#define BKTILE 32
#define PADH   40   // halves per smem row (32 + 8 pad) -> conflict-free ldmatrix

__device__ __forceinline__ void gemm_128x64(
    const __half* __restrict__ Ag, const __half* __restrict__ Bg,
    int m0, int n0, float (&C)[4][4][4], __half* As, __half* Bs)
{
    const int tid  = threadIdx.x;
    const int lane = tid & 31;
    const int warp = tid >> 5;
    const int wm = (warp >> 1) * 64;
    const int wn = (warp & 1) * 32;

    // ldmatrix per-lane offsets (same formula for A and B tiles)
    const int lrow = (lane & 7) + ((lane >> 3) & 1) * 8;
    const int lcol = ((lane >> 4) & 1) * 8;

    // stage loader: 512 A-chunks + 256 B-chunks of 16B, 6 per thread
    auto load_stage = [&](int s, int kk) {
        unsigned sa = smem_u32(As + s * 128 * PADH);
        unsigned sb = smem_u32(Bs + s * 64 * PADH);
#pragma unroll
        for (int j = 0; j < 6; ++j) {
            int ci = tid + j * 128;
            if (ci < 512) {
                int r = ci >> 2, c = ci & 3;
                cp_async16(sa + (unsigned)(r * PADH + c * 8) * 2,
                           Ag + (size_t)(m0 + r) * 1024 + kk + c * 8);
            } else {
                int ci2 = ci - 512;
                int r = ci2 >> 2, c = ci2 & 3;
                cp_async16(sb + (unsigned)(r * PADH + c * 8) * 2,
                           Bg + (size_t)(n0 + r) * 1024 + kk + c * 8);
            }
        }
        cp_commit();
    };

    load_stage(0, 0);

#pragma unroll 1
    for (int ki = 0; ki < 32; ++ki) {
        cp_wait0();
        __syncthreads();
        if (ki < 31) load_stage((ki + 1) & 1, (ki + 1) * BKTILE);

        const __half* Ab = As + (ki & 1) * 128 * PADH;
        const __half* Bb = Bs + (ki & 1) * 64 * PADH;

#pragma unroll
        for (int kc = 0; kc < 2; ++kc) {
            unsigned a[4][4], b[4][2];
#pragma unroll
            for (int mt = 0; mt < 4; ++mt) {
                unsigned ad = smem_u32(Ab + (wm + mt * 16 + lrow) * PADH + kc * 16 + lcol);
                ldmatrix_x4(a[mt][0], a[mt][1], a[mt][2], a[mt][3], ad);
            }
#pragma unroll
            for (int p = 0; p < 2; ++p) {
                unsigned bd = smem_u32(Bb + (wn + p * 16 + lrow) * PADH + kc * 16 + lcol);
                unsigned r0, r1, r2, r3;
                ldmatrix_x4(r0, r1, r2, r3, bd);
                b[2 * p][0] = r0; b[2 * p][1] = r2;
                b[2 * p + 1][0] = r1; b[2 * p + 1][1] = r3;
            }
#pragma unroll
            for (int mt = 0; mt < 4; ++mt)
#pragma unroll
                for (int nt = 0; nt < 4; ++nt)
                    mma16816(C[mt][nt], a[mt], b[nt]);
        }
    }
}

// ---------------- xproj GEMM: g_xproj = g_xh @ W_ih^T + bias ----------------
__global__ void __launch_bounds__(128) xproj_kernel() {
    __shared__ __align__(16) __half As[2 * 128 * PADH];
    __shared__ __align__(16) __half Bs[2 * 64 * PADH];
    float C[4][4][4] = {};
    const int m0 = blockIdx.x * 128;
    const int n0 = blockIdx.y * 64;
    gemm_128x64(g_xh, g_wih, m0, n0, C, As, Bs);

    const int lane = threadIdx.x & 31, warp = threadIdx.x >> 5;
    const int wm = (warp >> 1) * 64, wn = (warp & 1) * 32;
    const int gid = lane >> 2, t4 = lane & 3;
#pragma unroll
    for (int mt = 0; mt < 4; ++mt)
#pragma unroll
        for (int nt = 0; nt < 4; ++nt) {
            int n = n0 + wn + nt * 8 + t4 * 2;
            float b0 = g_bias[n], b1 = g_bias[n + 1];
            int m = m0 + wm + mt * 16 + gid;
            float2 v0 = { C[mt][nt][0] + b0, C[mt][nt][1] + b1 };
            float2 v1 = { C[mt][nt][2] + b0, C[mt][nt][3] + b1 };
            *(float2*)&g_xproj[(size_t)m * 1024 + n]       = v0;
            *(float2*)&g_xproj[(size_t)(m + 8) * 1024 + n] = v1;
        }
}

// ---------------- recurrence step: h = tanh(xproj_t + h @ W_hh^T) ----------------
// Row m of the 1024-row batch = sequence n: b = m>>4, c = m&15, time l = 127 - t.
// xproj row  = b*2048 +      c *128 + l
// output row = b*2048 + (15-c)*128 + l   (chunk order reversed in output)
__global__ void __launch_bounds__(128) step_kernel(float* __restrict__ out, int t) {
    __shared__ __align__(16) __half As[2 * 128 * PADH];
    __shared__ __align__(16) __half Bs[2 * 64 * PADH];
    float C[4][4][4] = {};
    const int m0 = blockIdx.x * 128;
    const int n0 = blockIdx.y * 64;
    const __half* Hprev = g_hbuf[t & 1];
    __half* Hnext = g_hbuf[(t + 1) & 1];
    gemm_128x64(Hprev, g_whh, m0, n0, C, As, Bs);

    const int lane = threadIdx.x & 31, warp = threadIdx.x >> 5;
    const int wm = (warp >> 1) * 64, wn = (warp & 1) * 32;
    const int gid = lane >> 2, t4 = lane & 3;
    const int l = 127 - t;

#pragma unroll
    for (int mt = 0; mt < 4; ++mt)
#pragma unroll
        for (int nt = 0; nt < 4; ++nt) {
            int n = n0 + wn + nt * 8 + t4 * 2;
#pragma unroll
            for (int half_m = 0; half_m < 2; ++half_m) {
                int m = m0 + wm + mt * 16 + gid + half_m * 8;   // sequence id
                int b = m >> 4, c = m & 15;
                size_t xrow = ((size_t)b * 2048 + c * 128 + l) * 1024;
                size_t orow = ((size_t)b * 2048 + (15 - c) * 128 + l) * 1024;
                float z0 = C[mt][nt][2 * half_m + 0] + g_xproj[xrow + n];
                float z1 = C[mt][nt][2 * half_m + 1] + g_xproj[xrow + n + 1];
                float h0 = tanhf(z0);
                float h1 = tanhf(z1);
                float2 vo = { h0, h1 };
                *(float2*)&out[orow + n] = vo;
                *(__half2*)&Hnext[(size_t)m * 1024 + n] = __floats2half2_rn(h0, h1);
            }
        }
}

// ---------------- h_final = out[b, 0, :] ----------------
__global__ void hfinal_kernel(float* __restrict__ out) {
    int i = blockIdx.x * blockDim.x + threadIdx.x;   // 0 .. 65535
    int b = i >> 10, h = i & 1023;
    out[(size_t)Bsz * Ssz * Hsz + i] = out[(size_t)b * Ssz * Hsz + h];
}

// ---------------- launch ----------------
extern "C" void kernel_launch(void* const* d_in, const int* in_sizes, int n_in,
                              void* d_out, int out_size) {
    const float* x   = (const float*)d_in[0];
    // d_in[1] = hidden_state (unused: every chunk starts from zeros per reference)
    const float* wih = (const float*)d_in[2];
    const float* whh = (const float*)d_in[3];
    const float* bih = (const float*)d_in[4];
    const float* bhh = (const float*)d_in[5];
    float* out = (float*)d_out;

    convert_x_kernel<<<131072, 256>>>(x);
    prep_kernel<<<4096, 256>>>(wih, whh, bih, bhh);

    dim3 gx(MROWS / 128, Hsz / 64);   // (1024, 16)
    xproj_kernel<<<gx, 128>>>();

    dim3 gs(NSEQ / 128, Hsz / 64);    // (8, 16)
    for (int t = 0; t < Lsz; ++t)
        step_kernel<<<gs, 128>>>(out, t);

    if (out_size > Bsz * Ssz * Hsz)
        hfinal_kernel<<<64, 1024>>>(out);
}

// round 8
// speedup vs baseline: 1.3390x; 1.3390x over previous
#include <cuda_runtime.h>
#include <cuda_fp16.h>

// Problem constants
#define Bsz 64
#define Ssz 2048
#define Fsz 1024
#define Hsz 1024
#define Lsz 128
#define NCsz 16
#define MROWS (Bsz * Ssz)   // 131072
#define NSEQ  (Bsz * NCsz)  // 1024

// ---------------- scratch (static device allocations) ----------------
__device__ __half g_xh[(size_t)MROWS * Fsz];      // 256 MB  fp16 inputs
__device__ float  g_xproj[(size_t)MROWS * Hsz];   // 512 MB  x @ W_ih^T + bias
__device__ __half g_wih[Hsz * Fsz];               // 2 MB
__device__ __half g_whh[Hsz * Hsz];               // 2 MB
__device__ __half g_hbuf[2][NSEQ * Hsz];          // 4 MB ping-pong hidden state
__device__ float  g_bias[Hsz];
__device__ unsigned g_arrive;                     // grid barrier counter

// ---------------- small helpers ----------------
__device__ __forceinline__ unsigned smem_u32(const void* p) {
    return (unsigned)__cvta_generic_to_shared(p);
}
__device__ __forceinline__ void ldmatrix_x4(unsigned& r0, unsigned& r1, unsigned& r2, unsigned& r3, unsigned addr) {
    asm volatile("ldmatrix.sync.aligned.m8n8.x4.shared.b16 {%0,%1,%2,%3}, [%4];\n"
                 : "=r"(r0), "=r"(r1), "=r"(r2), "=r"(r3) : "r"(addr));
}
__device__ __forceinline__ void mma16816(float* c, const unsigned* a, const unsigned* b) {
    asm volatile("mma.sync.aligned.m16n8k16.row.col.f32.f16.f16.f32 "
                 "{%0,%1,%2,%3}, {%4,%5,%6,%7}, {%8,%9}, {%0,%1,%2,%3};\n"
                 : "+f"(c[0]), "+f"(c[1]), "+f"(c[2]), "+f"(c[3])
                 : "r"(a[0]), "r"(a[1]), "r"(a[2]), "r"(a[3]), "r"(b[0]), "r"(b[1]));
}
__device__ __forceinline__ void cp_async16(unsigned saddr, const void* gaddr) {
    asm volatile("cp.async.cg.shared.global [%0], [%1], 16;\n" :: "r"(saddr), "l"(gaddr));
}
__device__ __forceinline__ void cp_commit() { asm volatile("cp.async.commit_group;\n"); }
__device__ __forceinline__ void cp_wait0()  { asm volatile("cp.async.wait_group 0;\n"); }
__device__ __forceinline__ void cp_wait1()  { asm volatile("cp.async.wait_group 1;\n"); }

// ---------------- conversion / prep kernels ----------------
__global__ void convert_x_kernel(const float* __restrict__ x) {
    size_t i = ((size_t)blockIdx.x * blockDim.x + threadIdx.x) * 4;
    float4 v = *(const float4*)(x + i);
    *(__half2*)(g_xh + i)     = __floats2half2_rn(v.x, v.y);
    *(__half2*)(g_xh + i + 2) = __floats2half2_rn(v.z, v.w);
}

__global__ void prep_kernel(const float* __restrict__ wih, const float* __restrict__ whh,
                            const float* __restrict__ bih, const float* __restrict__ bhh) {
    int i = blockIdx.x * blockDim.x + threadIdx.x;   // 0 .. 1048575
    g_wih[i] = __float2half_rn(wih[i]);
    g_whh[i] = __float2half_rn(whh[i]);
    g_hbuf[0][i] = __float2half_rn(0.0f);
    if (i < Hsz) g_bias[i] = bih[i] + bhh[i];
    if (i == 0) g_arrive = 0u;
}

// ---------------- 128x64 GEMM mainloop for xproj (unchanged, known-good) ----------------
#define BKTILE 32
#define PADH   40   // halves per smem row (32 + 8 pad)

__device__ __forceinline__ void gemm_128x64(
    const __half* __restrict__ Ag, const __half* __restrict__ Bg,
    int m0, int n0, float (&C)[4][4][4], __half* As, __half* Bs)
{
    const int tid  = threadIdx.x;
    const int lane = tid & 31;
    const int warp = tid >> 5;
    const int wm = (warp >> 1) * 64;
    const int wn = (warp & 1) * 32;
    const int lrow = (lane & 7) + ((lane >> 3) & 1) * 8;
    const int lcol = ((lane >> 4) & 1) * 8;

    auto load_stage = [&](int s, int kk) {
        unsigned sa = smem_u32(As + s * 128 * PADH);
        unsigned sb = smem_u32(Bs + s * 64 * PADH);
#pragma unroll
        for (int j = 0; j < 6; ++j) {
            int ci = tid + j * 128;
            if (ci < 512) {
                int r = ci >> 2, c = ci & 3;
                cp_async16(sa + (unsigned)(r * PADH + c * 8) * 2,
                           Ag + (size_t)(m0 + r) * 1024 + kk + c * 8);
            } else {
                int ci2 = ci - 512;
                int r = ci2 >> 2, c = ci2 & 3;
                cp_async16(sb + (unsigned)(r * PADH + c * 8) * 2,
                           Bg + (size_t)(n0 + r) * 1024 + kk + c * 8);
            }
        }
        cp_commit();
    };

    load_stage(0, 0);

#pragma unroll 1
    for (int ki = 0; ki < 32; ++ki) {
        cp_wait0();
        __syncthreads();
        if (ki < 31) load_stage((ki + 1) & 1, (ki + 1) * BKTILE);

        const __half* Ab = As + (ki & 1) * 128 * PADH;
        const __half* Bb = Bs + (ki & 1) * 64 * PADH;

#pragma unroll
        for (int kc = 0; kc < 2; ++kc) {
            unsigned a[4][4], b[4][2];
#pragma unroll
            for (int mt = 0; mt < 4; ++mt) {
                unsigned ad = smem_u32(Ab + (wm + mt * 16 + lrow) * PADH + kc * 16 + lcol);
                ldmatrix_x4(a[mt][0], a[mt][1], a[mt][2], a[mt][3], ad);
            }
#pragma unroll
            for (int p = 0; p < 2; ++p) {
                unsigned bd = smem_u32(Bb + (wn + p * 16 + lrow) * PADH + kc * 16 + lcol);
                unsigned r0, r1, r2, r3;
                ldmatrix_x4(r0, r1, r2, r3, bd);
                b[2 * p][0] = r0; b[2 * p][1] = r2;
                b[2 * p + 1][0] = r1; b[2 * p + 1][1] = r3;
            }
#pragma unroll
            for (int mt = 0; mt < 4; ++mt)
#pragma unroll
                for (int nt = 0; nt < 4; ++nt)
                    mma16816(C[mt][nt], a[mt], b[nt]);
        }
    }
}

// ---------------- xproj GEMM: g_xproj = g_xh @ W_ih^T + bias ----------------
__global__ void __launch_bounds__(128) xproj_kernel() {
    __shared__ __align__(16) __half As[2 * 128 * PADH];
    __shared__ __align__(16) __half Bs[2 * 64 * PADH];
    float C[4][4][4] = {};
    const int m0 = blockIdx.x * 128;
    const int n0 = blockIdx.y * 64;
    gemm_128x64(g_xh, g_wih, m0, n0, C, As, Bs);

    const int lane = threadIdx.x & 31, warp = threadIdx.x >> 5;
    const int wm = (warp >> 1) * 64, wn = (warp & 1) * 32;
    const int gid = lane >> 2, t4 = lane & 3;
#pragma unroll
    for (int mt = 0; mt < 4; ++mt)
#pragma unroll
        for (int nt = 0; nt < 4; ++nt) {
            int n = n0 + wn + nt * 8 + t4 * 2;
            float b0 = g_bias[n], b1 = g_bias[n + 1];
            int m = m0 + wm + mt * 16 + gid;
            float2 v0 = { C[mt][nt][0] + b0, C[mt][nt][1] + b1 };
            float2 v1 = { C[mt][nt][2] + b0, C[mt][nt][3] + b1 };
            *(float2*)&g_xproj[(size_t)m * 1024 + n]       = v0;
            *(float2*)&g_xproj[(size_t)(m + 8) * 1024 + n] = v1;
        }
}

// ---------------- persistent scan kernel ----------------
// Grid = 128 blocks (all co-resident on 148 SMs), 256 threads = 8 warps (2x4).
// Each block owns output tile (m0: 128 seqs, n0: 64 hidden cols) and keeps its
// 64x1024 W_hh slice in shared memory for the whole scan. Steps separated by a
// software grid barrier on an atomic counter (reset by prep_kernel per replay).
#define BK2     64
#define APAD    72      // 64 + 8 halves per A smem row
#define WPITCH  1032    // 1024 + 8 halves per W smem row
#define SMEM_SCAN_BYTES ((64 * WPITCH + 2 * 128 * APAD) * 2)

__global__ void __launch_bounds__(256) scan_kernel(float* __restrict__ out) {
    extern __shared__ __align__(16) __half smem[];
    __half* Ws = smem;                       // [64][WPITCH]
    __half* As = smem + 64 * WPITCH;         // [2][128][APAD]

    const int tid  = threadIdx.x;
    const int lane = tid & 31;
    const int warp = tid >> 5;
    const int m0 = (blockIdx.x & 7) * 128;
    const int n0 = (blockIdx.x >> 3) * 64;
    const int wm = (warp >> 2) * 64;         // 0 or 64
    const int wn = (warp & 3) * 16;          // 0,16,32,48
    const int lrow = (lane & 7) + ((lane >> 3) & 1) * 8;
    const int lcol = ((lane >> 4) & 1) * 8;
    const int gid = lane >> 2, t4 = lane & 3;

    // Load resident W_hh slice: rows n0..n0+63, full K.
    for (int j = tid; j < 64 * 128; j += 256) {       // 64 rows x 128 chunks of 8 halves
        int r = j >> 7, c = j & 127;
        cp_async16(smem_u32(Ws + r * WPITCH + c * 8),
                   g_whh + (size_t)(n0 + r) * 1024 + c * 8);
    }
    cp_commit();

    const unsigned NB = gridDim.x;

    for (int t = 0; t < Lsz; ++t) {
        const __half* Hprev = g_hbuf[t & 1];
        __half* Hnext = g_hbuf[(t + 1) & 1];
        float C[4][2][4] = {};

        // ---- A stage loader: 128 rows x BK2 halves into buffer `s` (0/1) ----
        auto loadA = [&](int s, int kk) {
            unsigned sa = smem_u32(As + s * 128 * APAD);
#pragma unroll
            for (int j = 0; j < 4; ++j) {
                int ci = tid + j * 256;                // 0..1023
                int r = ci >> 3, c = ci & 7;
                cp_async16(sa + (unsigned)(r * APAD + c * 8) * 2,
                           Hprev + (size_t)(m0 + r) * 1024 + kk + c * 8);
            }
            cp_commit();
        };

        loadA(0, 0);
#pragma unroll 1
        for (int s = 0; s < 16; ++s) {
            if (s < 15) { loadA((s + 1) & 1, (s + 1) * BK2); cp_wait1(); }  // FIX: buffer index mod 2
            else        { cp_wait0(); }
            __syncthreads();

            const __half* Ab = As + (s & 1) * 128 * APAD;
#pragma unroll
            for (int kc = 0; kc < 4; ++kc) {
                const int kofs = kc * 16;
                unsigned a[4][4];
#pragma unroll
                for (int mt = 0; mt < 4; ++mt)
                    ldmatrix_x4(a[mt][0], a[mt][1], a[mt][2], a[mt][3],
                                smem_u32(Ab + (wm + mt * 16 + lrow) * APAD + kofs + lcol));
                unsigned r0, r1, r2, r3;
                ldmatrix_x4(r0, r1, r2, r3,
                            smem_u32(Ws + (wn + lrow) * WPITCH + s * BK2 + kofs + lcol));
                unsigned b0[2] = { r0, r2 };
                unsigned b1[2] = { r1, r3 };
#pragma unroll
                for (int mt = 0; mt < 4; ++mt) {
                    mma16816(C[mt][0], a[mt], b0);
                    mma16816(C[mt][1], a[mt], b1);
                }
            }
            __syncthreads();
        }

        // ---- epilogue: h = tanh(C + xproj_t); scatter to out; store Hnext ----
        const int l = 127 - t;
#pragma unroll
        for (int mt = 0; mt < 4; ++mt)
#pragma unroll
            for (int nt = 0; nt < 2; ++nt) {
                int n = n0 + wn + nt * 8 + t4 * 2;
#pragma unroll
                for (int hm = 0; hm < 2; ++hm) {
                    int m = m0 + wm + mt * 16 + gid + hm * 8;   // sequence id
                    int b = m >> 4, c = m & 15;
                    size_t xrow = ((size_t)b * 2048 + c * 128 + l) * 1024;
                    size_t orow = ((size_t)b * 2048 + (15 - c) * 128 + l) * 1024;
                    float z0 = C[mt][nt][2 * hm + 0] + g_xproj[xrow + n];
                    float z1 = C[mt][nt][2 * hm + 1] + g_xproj[xrow + n + 1];
                    float h0 = tanhf(z0);
                    float h1 = tanhf(z1);
                    float2 vo = { h0, h1 };
                    *(float2*)&out[orow + n] = vo;
                    *(__half2*)&Hnext[(size_t)m * 1024 + n] = __floats2half2_rn(h0, h1);
                }
            }

        // ---- grid barrier (release Hnext, then wait for all blocks) ----
        __threadfence();
        __syncthreads();
        if (tid == 0) {
            atomicAdd(&g_arrive, 1u);
            unsigned tgt = (unsigned)(t + 1) * NB;
            while (atomicAdd(&g_arrive, 0u) < tgt) { }
        }
        __syncthreads();
        __threadfence();
        // Next step's A loads use cp.async.cg (L1-bypassing) so cross-SM
        // Hnext writes are read coherently from L2.
    }
}

// ---------------- h_final = out[b, 0, :] ----------------
__global__ void hfinal_kernel(float* __restrict__ out) {
    int i = blockIdx.x * blockDim.x + threadIdx.x;   // 0 .. 65535
    int b = i >> 10, h = i & 1023;
    out[(size_t)Bsz * Ssz * Hsz + i] = out[(size_t)b * Ssz * Hsz + h];
}

// ---------------- launch ----------------
extern "C" void kernel_launch(void* const* d_in, const int* in_sizes, int n_in,
                              void* d_out, int out_size) {
    const float* x   = (const float*)d_in[0];
    // d_in[1] = hidden_state (unused: every chunk starts from zeros per reference)
    const float* wih = (const float*)d_in[2];
    const float* whh = (const float*)d_in[3];
    const float* bih = (const float*)d_in[4];
    const float* bhh = (const float*)d_in[5];
    float* out = (float*)d_out;

    cudaFuncSetAttribute(scan_kernel, cudaFuncAttributeMaxDynamicSharedMemorySize,
                         SMEM_SCAN_BYTES);

    convert_x_kernel<<<131072, 256>>>(x);
    prep_kernel<<<4096, 256>>>(wih, whh, bih, bhh);

    dim3 gx(MROWS / 128, Hsz / 64);   // (1024, 16)
    xproj_kernel<<<gx, 128>>>();

    scan_kernel<<<128, 256, SMEM_SCAN_BYTES>>>(out);

    if (out_size > Bsz * Ssz * Hsz)
        hfinal_kernel<<<64, 1024>>>(out);
}

// round 9
// speedup vs baseline: 1.7810x; 1.3301x over previous
#include <cuda_runtime.h>
#include <cuda_fp16.h>

// Problem constants
#define Bsz 64
#define Ssz 2048
#define Fsz 1024
#define Hsz 1024
#define Lsz 128
#define NCsz 16
#define MROWS (Bsz * Ssz)   // 131072
#define NSEQ  (Bsz * NCsz)  // 1024

// ---------------- scratch (static device allocations) ----------------
__device__ __half g_xh[(size_t)MROWS * Fsz];      // 256 MB  fp16 inputs
__device__ __half g_xproj[(size_t)MROWS * Hsz];   // 256 MB  fp16 x @ W_ih^T + bias
__device__ __half g_wih[Hsz * Fsz];               // 2 MB
__device__ __half g_whh[Hsz * Hsz];               // 2 MB
__device__ __half g_hbuf[2][NSEQ * Hsz];          // 4 MB ping-pong hidden state
__device__ float  g_bias[Hsz];
__device__ unsigned g_arrive;                     // grid barrier counter

// ---------------- small helpers ----------------
__device__ __forceinline__ unsigned smem_u32(const void* p) {
    return (unsigned)__cvta_generic_to_shared(p);
}
__device__ __forceinline__ void ldmatrix_x4(unsigned& r0, unsigned& r1, unsigned& r2, unsigned& r3, unsigned addr) {
    asm volatile("ldmatrix.sync.aligned.m8n8.x4.shared.b16 {%0,%1,%2,%3}, [%4];\n"
                 : "=r"(r0), "=r"(r1), "=r"(r2), "=r"(r3) : "r"(addr));
}
__device__ __forceinline__ void mma16816(float* c, const unsigned* a, const unsigned* b) {
    asm volatile("mma.sync.aligned.m16n8k16.row.col.f32.f16.f16.f32 "
                 "{%0,%1,%2,%3}, {%4,%5,%6,%7}, {%8,%9}, {%0,%1,%2,%3};\n"
                 : "+f"(c[0]), "+f"(c[1]), "+f"(c[2]), "+f"(c[3])
                 : "r"(a[0]), "r"(a[1]), "r"(a[2]), "r"(a[3]), "r"(b[0]), "r"(b[1]));
}
__device__ __forceinline__ void cp_async16(unsigned saddr, const void* gaddr) {
    asm volatile("cp.async.cg.shared.global [%0], [%1], 16;\n" :: "r"(saddr), "l"(gaddr));
}
__device__ __forceinline__ void cp_commit() { asm volatile("cp.async.commit_group;\n"); }
__device__ __forceinline__ void cp_wait0()  { asm volatile("cp.async.wait_group 0;\n"); }
__device__ __forceinline__ void cp_wait1()  { asm volatile("cp.async.wait_group 1;\n"); }

// ---------------- conversion / prep kernels ----------------
__global__ void convert_x_kernel(const float* __restrict__ x) {
    size_t i = ((size_t)blockIdx.x * blockDim.x + threadIdx.x) * 4;
    float4 v = *(const float4*)(x + i);
    *(__half2*)(g_xh + i)     = __floats2half2_rn(v.x, v.y);
    *(__half2*)(g_xh + i + 2) = __floats2half2_rn(v.z, v.w);
}

__global__ void prep_kernel(const float* __restrict__ wih, const float* __restrict__ whh,
                            const float* __restrict__ bih, const float* __restrict__ bhh) {
    int i = blockIdx.x * blockDim.x + threadIdx.x;   // 0 .. 1048575
    g_wih[i] = __float2half_rn(wih[i]);
    g_whh[i] = __float2half_rn(whh[i]);
    g_hbuf[0][i] = __float2half_rn(0.0f);
    if (i < Hsz) g_bias[i] = bih[i] + bhh[i];
    if (i == 0) g_arrive = 0u;
}

// ---------------- 128x64 GEMM mainloop for xproj (3-stage, 1 sync/iter) ----------------
#define BKTILE 32
#define PADH   40   // halves per smem row (32 + 8 pad)

__device__ __forceinline__ void gemm_128x64(
    const __half* __restrict__ Ag, const __half* __restrict__ Bg,
    int m0, int n0, float (&C)[4][4][4], __half* As, __half* Bs)
{
    const int tid  = threadIdx.x;
    const int lane = tid & 31;
    const int warp = tid >> 5;
    const int wm = (warp >> 1) * 64;
    const int wn = (warp & 1) * 32;
    const int lrow = (lane & 7) + ((lane >> 3) & 1) * 8;
    const int lcol = ((lane >> 4) & 1) * 8;

    auto load_stage = [&](int s, int kk) {
        unsigned sa = smem_u32(As + s * 128 * PADH);
        unsigned sb = smem_u32(Bs + s * 64 * PADH);
#pragma unroll
        for (int j = 0; j < 6; ++j) {
            int ci = tid + j * 128;
            if (ci < 512) {
                int r = ci >> 2, c = ci & 3;
                cp_async16(sa + (unsigned)(r * PADH + c * 8) * 2,
                           Ag + (size_t)(m0 + r) * 1024 + kk + c * 8);
            } else {
                int ci2 = ci - 512;
                int r = ci2 >> 2, c = ci2 & 3;
                cp_async16(sb + (unsigned)(r * PADH + c * 8) * 2,
                           Bg + (size_t)(n0 + r) * 1024 + kk + c * 8);
            }
        }
        cp_commit();
    };

    load_stage(0, 0);
    load_stage(1, BKTILE);

#pragma unroll 1
    for (int ki = 0; ki < 32; ++ki) {
        if (ki < 31) cp_wait1(); else cp_wait0();
        __syncthreads();
        // Safe to issue into buffer (ki+2)%3 == (ki-1)%3 here: compute of
        // stage ki-1 is barrier-ordered before this point for all warps.
        if (ki + 2 < 32) load_stage((ki + 2) % 3, (ki + 2) * BKTILE);

        const __half* Ab = As + (ki % 3) * 128 * PADH;
        const __half* Bb = Bs + (ki % 3) * 64 * PADH;

#pragma unroll
        for (int kc = 0; kc < 2; ++kc) {
            unsigned a[4][4], b[4][2];
#pragma unroll
            for (int mt = 0; mt < 4; ++mt) {
                unsigned ad = smem_u32(Ab + (wm + mt * 16 + lrow) * PADH + kc * 16 + lcol);
                ldmatrix_x4(a[mt][0], a[mt][1], a[mt][2], a[mt][3], ad);
            }
#pragma unroll
            for (int p = 0; p < 2; ++p) {
                unsigned bd = smem_u32(Bb + (wn + p * 16 + lrow) * PADH + kc * 16 + lcol);
                unsigned r0, r1, r2, r3;
                ldmatrix_x4(r0, r1, r2, r3, bd);
                b[2 * p][0] = r0; b[2 * p][1] = r2;
                b[2 * p + 1][0] = r1; b[2 * p + 1][1] = r3;
            }
#pragma unroll
            for (int mt = 0; mt < 4; ++mt)
#pragma unroll
                for (int nt = 0; nt < 4; ++nt)
                    mma16816(C[mt][nt], a[mt], b[nt]);
        }
    }
}

// ---------------- xproj GEMM: g_xproj = fp16(g_xh @ W_ih^T + bias) ----------------
// Grid transposed: blockIdx.x = n-tile (fast), blockIdx.y = m-tile, so a wave of
// ~148 co-resident blocks shares ~9 A m-tiles through L2 (16x A-traffic cut).
__global__ void __launch_bounds__(128) xproj_kernel() {
    __shared__ __align__(16) __half As[3 * 128 * PADH];
    __shared__ __align__(16) __half Bs[3 * 64 * PADH];
    float C[4][4][4] = {};
    const int m0 = blockIdx.y * 128;
    const int n0 = blockIdx.x * 64;
    gemm_128x64(g_xh, g_wih, m0, n0, C, As, Bs);

    const int lane = threadIdx.x & 31, warp = threadIdx.x >> 5;
    const int wm = (warp >> 1) * 64, wn = (warp & 1) * 32;
    const int gid = lane >> 2, t4 = lane & 3;
#pragma unroll
    for (int mt = 0; mt < 4; ++mt)
#pragma unroll
        for (int nt = 0; nt < 4; ++nt) {
            int n = n0 + wn + nt * 8 + t4 * 2;
            float b0 = g_bias[n], b1 = g_bias[n + 1];
            int m = m0 + wm + mt * 16 + gid;
            *(__half2*)&g_xproj[(size_t)m * 1024 + n] =
                __floats2half2_rn(C[mt][nt][0] + b0, C[mt][nt][1] + b1);
            *(__half2*)&g_xproj[(size_t)(m + 8) * 1024 + n] =
                __floats2half2_rn(C[mt][nt][2] + b0, C[mt][nt][3] + b1);
        }
}

// ---------------- persistent scan kernel ----------------
// Grid = 128 blocks (all co-resident), 256 threads = 8 warps (2x4 warp grid).
// W_hh slice (64x1024) resident in smem; 3-stage A pipeline, 1 sync per k-iter;
// xproj epilogue operands prefetched before the mainloop; volatile-poll barrier.
#define BK2     64
#define APAD    72      // 64 + 8 halves per A smem row
#define WPITCH  1032    // 1024 + 8 halves per W smem row
#define SMEM_SCAN_BYTES ((64 * WPITCH + 3 * 128 * APAD) * 2)

__global__ void __launch_bounds__(256) scan_kernel(float* __restrict__ out) {
    extern __shared__ __align__(16) __half smem[];
    __half* Ws = smem;                       // [64][WPITCH]
    __half* As = smem + 64 * WPITCH;         // [3][128][APAD]

    const int tid  = threadIdx.x;
    const int lane = tid & 31;
    const int warp = tid >> 5;
    const int m0 = (blockIdx.x & 7) * 128;
    const int n0 = (blockIdx.x >> 3) * 64;
    const int wm = (warp >> 2) * 64;         // 0 or 64
    const int wn = (warp & 3) * 16;          // 0,16,32,48
    const int lrow = (lane & 7) + ((lane >> 3) & 1) * 8;
    const int lcol = ((lane >> 4) & 1) * 8;
    const int gid = lane >> 2, t4 = lane & 3;

    // Load resident W_hh slice: rows n0..n0+63, full K.
    for (int j = tid; j < 64 * 128; j += 256) {       // 64 rows x 128 chunks of 8 halves
        int r = j >> 7, c = j & 127;
        cp_async16(smem_u32(Ws + r * WPITCH + c * 8),
                   g_whh + (size_t)(n0 + r) * 1024 + c * 8);
    }
    cp_commit();

    const unsigned NB = gridDim.x;

    // Per-thread epilogue geometry (constant across steps except l).
    int mseq[4][2];         // sequence ids
    size_t xbase[4][2], obase[4][2];
#pragma unroll
    for (int mt = 0; mt < 4; ++mt)
#pragma unroll
        for (int hm = 0; hm < 2; ++hm) {
            int m = m0 + wm + mt * 16 + gid + hm * 8;
            int b = m >> 4, c = m & 15;
            mseq[mt][hm] = m;
            xbase[mt][hm] = ((size_t)b * 2048 + c * 128) * 1024;
            obase[mt][hm] = ((size_t)b * 2048 + (15 - c) * 128) * 1024;
        }

    for (int t = 0; t < Lsz; ++t) {
        const __half* Hprev = g_hbuf[t & 1];
        __half* Hnext = g_hbuf[(t + 1) & 1];
        float C[4][2][4] = {};
        const int l = 127 - t;

        // ---- prefetch xproj epilogue operands (independent of h) ----
        unsigned xp[4][2][2];   // [mt][nt][hm] packed half2
#pragma unroll
        for (int mt = 0; mt < 4; ++mt)
#pragma unroll
            for (int nt = 0; nt < 2; ++nt) {
                int n = n0 + wn + nt * 8 + t4 * 2;
#pragma unroll
                for (int hm = 0; hm < 2; ++hm)
                    xp[mt][nt][hm] = __ldcs((const unsigned*)(g_xproj + xbase[mt][hm] + (size_t)l * 1024 + n));
            }

        // ---- A stage loader: 128 rows x BK2 halves into buffer s (0..2) ----
        auto loadA = [&](int s, int kk) {
            unsigned sa = smem_u32(As + s * 128 * APAD);
#pragma unroll
            for (int j = 0; j < 4; ++j) {
                int ci = tid + j * 256;                // 0..1023
                int r = ci >> 3, c = ci & 7;
                cp_async16(sa + (unsigned)(r * APAD + c * 8) * 2,
                           Hprev + (size_t)(m0 + r) * 1024 + kk + c * 8);
            }
            cp_commit();
        };

        loadA(0, 0);
        loadA(1, BK2);
#pragma unroll 1
        for (int s = 0; s < 16; ++s) {
            if (s < 15) cp_wait1(); else cp_wait0();
            __syncthreads();
            if (s + 2 < 16) loadA((s + 2) % 3, (s + 2) * BK2);

            const __half* Ab = As + (s % 3) * 128 * APAD;
#pragma unroll
            for (int kc = 0; kc < 4; ++kc) {
                const int kofs = kc * 16;
                unsigned a[4][4];
#pragma unroll
                for (int mt = 0; mt < 4; ++mt)
                    ldmatrix_x4(a[mt][0], a[mt][1], a[mt][2], a[mt][3],
                                smem_u32(Ab + (wm + mt * 16 + lrow) * APAD + kofs + lcol));
                unsigned r0, r1, r2, r3;
                ldmatrix_x4(r0, r1, r2, r3,
                            smem_u32(Ws + (wn + lrow) * WPITCH + s * BK2 + kofs + lcol));
                unsigned b0[2] = { r0, r2 };
                unsigned b1[2] = { r1, r3 };
#pragma unroll
                for (int mt = 0; mt < 4; ++mt) {
                    mma16816(C[mt][0], a[mt], b0);
                    mma16816(C[mt][1], a[mt], b1);
                }
            }
        }

        // ---- epilogue: h = tanh(C + xproj_t); scatter to out; store Hnext ----
#pragma unroll
        for (int mt = 0; mt < 4; ++mt)
#pragma unroll
            for (int nt = 0; nt < 2; ++nt) {
                int n = n0 + wn + nt * 8 + t4 * 2;
#pragma unroll
                for (int hm = 0; hm < 2; ++hm) {
                    float2 xf = __half22float2(*(__half2*)&xp[mt][nt][hm]);
                    float z0 = C[mt][nt][2 * hm + 0] + xf.x;
                    float z1 = C[mt][nt][2 * hm + 1] + xf.y;
                    float h0 = tanhf(z0);
                    float h1 = tanhf(z1);
                    size_t orow = obase[mt][hm] + (size_t)l * 1024;
                    float2 vo = { h0, h1 };
                    *(float2*)&out[orow + n] = vo;
                    *(__half2*)&Hnext[(size_t)mseq[mt][hm] * 1024 + n] = __floats2half2_rn(h0, h1);
                }
            }

        // ---- grid barrier (release Hnext, then wait for all blocks) ----
        __threadfence();
        __syncthreads();
        if (tid == 0) {
            atomicAdd(&g_arrive, 1u);
            unsigned tgt = (unsigned)(t + 1) * NB;
            while (*((volatile unsigned*)&g_arrive) < tgt) { }
        }
        __syncthreads();
        __threadfence();
        // Next step's A loads use cp.async.cg (L1-bypassing) so cross-SM
        // Hnext writes are read coherently from L2.
    }
}

// ---------------- h_final = out[b, 0, :] ----------------
__global__ void hfinal_kernel(float* __restrict__ out) {
    int i = blockIdx.x * blockDim.x + threadIdx.x;   // 0 .. 65535
    int b = i >> 10, h = i & 1023;
    out[(size_t)Bsz * Ssz * Hsz + i] = out[(size_t)b * Ssz * Hsz + h];
}

// ---------------- launch ----------------
extern "C" void kernel_launch(void* const* d_in, const int* in_sizes, int n_in,
                              void* d_out, int out_size) {
    const float* x   = (const float*)d_in[0];
    // d_in[1] = hidden_state (unused: every chunk starts from zeros per reference)
    const float* wih = (const float*)d_in[2];
    const float* whh = (const float*)d_in[3];
    const float* bih = (const float*)d_in[4];
    const float* bhh = (const float*)d_in[5];
    float* out = (float*)d_out;

    cudaFuncSetAttribute(scan_kernel, cudaFuncAttributeMaxDynamicSharedMemorySize,
                         SMEM_SCAN_BYTES);

    convert_x_kernel<<<131072, 256>>>(x);
    prep_kernel<<<4096, 256>>>(wih, whh, bih, bhh);

    dim3 gx(Hsz / 64, MROWS / 128);   // (16, 1024): n-tile fast for L2 A reuse
    xproj_kernel<<<gx, 128>>>();

    scan_kernel<<<128, 256, SMEM_SCAN_BYTES>>>(out);

    if (out_size > Bsz * Ssz * Hsz)
        hfinal_kernel<<<64, 1024>>>(out);
}